// round 16
// baseline (speedup 1.0000x reference)
#include <cuda_runtime.h>
#include <cuda_bf16.h>
#include <cstdint>

// ---------------------------------------------------------------------------
// Leaky CTRNN scan on HMMA (mma.sync m16n8k16 bf16, 3-term split).
// B=64 T=512 H=1024.  96 persistent blocks x 128 thr, 513 phases:
//   role0 (blk  0-31): fr0(p)   = relu(v0=.9v0+.1(Wrec0@fr0(p-1) + xin0)), K=1024
//   role1 (blk 32-95): fr1(p-1) = relu(v1=.9v1+.1([Wrec1|Win1]@[fr1(p-2);fr0(p-1)] + b1)), K=2048
// v15: NO per-phase grid barrier. Pure dataflow: per-(slot,chunk) release
// flags (atomicAdd by producers, ld.cg spin by the TMA issuer), blocks
// free-run. Flags zeroed at start + one startup barrier. Image slots are
// write-once per t (no WAR). Weights persist in smem bf16 hi/lo; fr streams
// via cp.async.bulk double-buffered; 3 separate accumulators.
// ---------------------------------------------------------------------------

namespace {
constexpr int B = 64, T = 512, DIN = 256, H = 1024, DOUT = 256;
constexpr float AL = 0.1f, OMA = 0.9f;
constexpr int NBLK = 96, THR = 128;
constexpr int CHB = 32768;               // fr chunk bytes: [2][64][256]
constexpr int SM_W  = 0;                 // weights: 131072 bytes
constexpr int SM_ST = 131072;            // staging: 2 x CHB
constexpr int SM_MB = SM_ST + 2 * CHB;   // 196608: two mbarriers
constexpr int SMEM_T = SM_MB + 64;
}

// GMEM scratch (allocation-free rule). Zero-initialized at module load;
// slot 0 of the images is never written, so it stays zero across replays.
__device__ float g_xin0[(size_t)T * H * B];                  // [t][h][b]
__device__ __align__(128) unsigned char g_f0img[513][8][CHB]; // slot t+1
__device__ __align__(128) unsigned char g_f1img[513][8][CHB];
__device__ unsigned g_fl0[513][8];        // producer-arrival counts per slot/chunk
__device__ unsigned g_fl1[513][8];
__device__ volatile unsigned g_gen;
__device__ unsigned g_cnt;

// ---- PTX helpers ------------------------------------------------------------
__device__ __forceinline__ void mbar_init(unsigned m, unsigned c) {
    asm volatile("mbarrier.init.shared.b64 [%0], %1;" :: "r"(m), "r"(c) : "memory");
}
__device__ __forceinline__ void mbar_tx(unsigned m, unsigned b) {
    asm volatile("mbarrier.arrive.expect_tx.shared.b64 _, [%0], %1;" :: "r"(m), "r"(b) : "memory");
}
__device__ __forceinline__ void bulk(unsigned d, const void* s, unsigned b, unsigned m) {
    asm volatile("cp.async.bulk.shared::cta.global.mbarrier::complete_tx::bytes [%0], [%1], %2, [%3];"
                 :: "r"(d), "l"(s), "r"(b), "r"(m) : "memory");
}
__device__ __forceinline__ void mwait(unsigned m, unsigned p) {
    asm volatile("{\n\t.reg .pred P;\nL_%=:\n\tmbarrier.try_wait.parity.shared.b64 P, [%0], %1;\n\t@!P bra L_%=;\n\t}"
                 :: "r"(m), "r"(p) : "memory");
}
__device__ __forceinline__ void ldsm4(uint32_t* r, unsigned a) {
    asm volatile("ldmatrix.sync.aligned.m8n8.x4.shared.b16 {%0,%1,%2,%3}, [%4];"
                 : "=r"(r[0]), "=r"(r[1]), "=r"(r[2]), "=r"(r[3]) : "r"(a));
}
__device__ __forceinline__ void mma16816(float* d, const uint32_t* a, const uint32_t* b) {
    asm volatile("mma.sync.aligned.m16n8k16.row.col.f32.bf16.bf16.f32 "
                 "{%0,%1,%2,%3},{%4,%5,%6,%7},{%8,%9},{%0,%1,%2,%3};"
                 : "+f"(d[0]), "+f"(d[1]), "+f"(d[2]), "+f"(d[3])
                 : "r"(a[0]), "r"(a[1]), "r"(a[2]), "r"(a[3]), "r"(b[0]), "r"(b[1]));
}
__device__ __forceinline__ void waitflag(const unsigned* f, unsigned exp) {
    unsigned x;
    while (true) {
        asm volatile("ld.global.cg.u32 %0, [%1];" : "=r"(x) : "l"(f));
        if (x >= exp) break;
        __nanosleep(32);
    }
}
__device__ __forceinline__ void gridbar() {
    __syncthreads();
    if (threadIdx.x == 0) {
        __threadfence();
        unsigned g = g_gen;
        if (atomicAdd(&g_cnt, 1u) == NBLK - 1) { g_cnt = 0; __threadfence(); g_gen = g + 1; }
        else { while (g_gen == g) { __nanosleep(64); } __threadfence(); }
    }
    __syncthreads();
}

// ---------------------------------------------------------------------------
__global__ void __launch_bounds__(THR, 1)
rnn_mma(const float* __restrict__ Wrec0, const float* __restrict__ Wrec1,
        const float* __restrict__ Win1, const float* __restrict__ b1,
        float* __restrict__ st0, float* __restrict__ st1)
{
    extern __shared__ unsigned char smc[];
    const unsigned sb = (unsigned)__cvta_generic_to_shared(smc);
    const int tid = threadIdx.x, wid = tid >> 5, lane = tid & 31, bid = blockIdx.x;
    const bool r0 = (bid < 32);
    const int HR = r0 ? 32 : 16;          // weight rows in smem tile
    const int PW = HR * 256;              // weight plane bytes
    const int CW = 2 * PW;                // weight chunk bytes
    const int NC = r0 ? 8 : 16;           // k-chunks per phase
    const int h0blk = r0 ? bid * 32 : (bid - 32) * 16;
    const int h0w = r0 ? (wid >> 1) * 16 : 0;      // warp m base (block-local)
    const int bn  = r0 ? (wid & 1) * 32 : wid * 16; // warp n base
    const int NT  = r0 ? 4 : 2;           // n8 tiles per warp
    const int NBF = NT >> 1;              // B ldmatrix.x4 per plane
    const int mychunk = h0blk >> 7;       // image chunk this block produces into
    const unsigned FEXP0 = 4, FEXP1 = 8;  // producers per chunk

    // --- zero flags (graph replays), then one startup barrier ---
    {
        unsigned* f0 = &g_fl0[0][0];
        unsigned* f1 = &g_fl1[0][0];
        for (int i = bid * THR + tid; i < 513 * 8; i += NBLK * THR) {
            f0[i] = 0; f1[i] = 0;
        }
    }

    // --- one-time: weights -> smem bf16 hi/lo, ldmatrix-swizzled ---
    {
        const int KT = r0 ? 1024 : 2048;
        for (int i = tid; i < HR * KT; i += THR) {
            int hl = i / KT, k = i - hl * KT;
            float val;
            if (r0) val = Wrec0[(size_t)(h0blk + hl) * H + k];
            else    val = (k < H) ? Wrec1[(size_t)(h0blk + hl) * H + k]
                                  : Win1[(size_t)(h0blk + hl) * H + (k - H)];
            __nv_bfloat16 hi = __float2bfloat16(val);
            __nv_bfloat16 lo = __float2bfloat16(val - __bfloat162float(hi));
            int c = k >> 7, kl = k & 127, u = kl >> 3;
            unsigned off = SM_W + (unsigned)c * CW + (unsigned)hl * 256
                         + ((unsigned)(u ^ (hl & 7)) << 4) + (kl & 7) * 2;
            *(__nv_bfloat16*)(smc + off) = hi;
            *(__nv_bfloat16*)(smc + off + PW) = lo;
        }
    }
    if (tid == 0) { mbar_init(sb + SM_MB, 1); mbar_init(sb + SM_MB + 8, 1); }
    asm volatile("fence.proxy.async.shared::cta;" ::: "memory");
    gridbar();   // flags zeroed everywhere before anyone runs

    // fragment address precompute
    const int ar  = h0w + (lane & 7) + ((lane >> 3) & 1) * 8;  // A row
    const int akh = (lane >> 4) & 1;
    const int ar7 = ar & 7;
    int brr[2], br7[2];
    #pragma unroll
    for (int f = 0; f < 2; f++) {
        brr[f] = bn + f * 16 + (lane & 7) + ((lane >> 4) & 1) * 8;
        br7[f] = brr[f] & 7;
    }
    const int bkh = (lane >> 3) & 1;

    float b1a = 0.f, b1b = 0.f;
    if (!r0) { b1a = b1[h0blk + (lane >> 2)]; b1b = b1[h0blk + (lane >> 2) + 8]; }

    unsigned par[2] = {0, 0};
    const unsigned mb[2]  = {sb + SM_MB, sb + SM_MB + 8};
    const unsigned stg[2] = {sb + SM_ST, sb + SM_ST + CHB};

    // epilogue staging (buffer 0 region)
    const int Wd = r0 ? 32 : 16;
    float* epf = (float*)(smc + SM_ST);
    __nv_bfloat16* ehi = (__nv_bfloat16*)(smc + SM_ST + 64 * Wd * 4);
    __nv_bfloat16* elo = ehi + 64 * Wd;

    float v[4][4];
    #pragma unroll
    for (int i = 0; i < 4; i++)
        #pragma unroll
        for (int j = 0; j < 4; j++) v[i][j] = 0.f;

    for (int p = 0; p <= T; p++) {
        const int t = r0 ? p : (p - 1);
        const bool act = r0 ? (p < T) : (p >= 1);
        if (act) {
            auto src = [&](int c) -> const void* {
                if (r0) return (const void*)g_f0img[p][c];        // fr0(p-1)
                return (c < 8) ? (const void*)g_f1img[t][c]        // fr1(t-1)
                               : (const void*)g_f0img[p][c - 8];   // fr0(p-1)
            };
            auto waitc = [&](int c) {
                if (r0) { if (p > 0) waitflag(&g_fl0[p][c], FEXP0); }
                else if (c < 8) { if (t > 0) waitflag(&g_fl1[t][c], FEXP1); }
                else waitflag(&g_fl0[p][c - 8], FEXP0);
            };
            if (tid == 0) {
                #pragma unroll
                for (int c = 0; c < 2; c++) {
                    waitc(c);
                    mbar_tx(mb[c], CHB);
                    bulk(stg[c], src(c), CHB, mb[c]);
                }
            }
            // 3 separate accumulator sets: 0 = hi*hi, 1 = hi*lo, 2 = lo*hi
            float d[3][4][4];
            #pragma unroll
            for (int e = 0; e < 3; e++)
                #pragma unroll
                for (int i = 0; i < 4; i++)
                    #pragma unroll
                    for (int j = 0; j < 4; j++) d[e][i][j] = 0.f;

            for (int c = 0; c < NC; c++) {
                const int bf = c & 1;
                mwait(mb[bf], par[bf]); par[bf] ^= 1;
                const unsigned wb = sb + SM_W + (unsigned)c * CW;
                const unsigned sg = stg[bf];
                #pragma unroll
                for (int ks = 0; ks < 8; ks++) {
                    uint32_t ahi[4], alo[4], bh[2][4], bl[2][4];
                    unsigned ua = ((unsigned)((ks * 2 + akh) ^ ar7)) << 4;
                    ldsm4(ahi, wb + (unsigned)ar * 256 + ua);
                    ldsm4(alo, wb + PW + (unsigned)ar * 256 + ua);
                    #pragma unroll
                    for (int f = 0; f < 2; f++) {
                        if (f >= NBF) break;
                        unsigned ub = ((unsigned)((ks * 2 + bkh) ^ br7[f])) << 4;
                        unsigned ba = sg + (unsigned)brr[f] * 256 + ub;
                        ldsm4(bh[f], ba);
                        ldsm4(bl[f], ba + 16384);
                    }
                    #pragma unroll
                    for (int nt = 0; nt < 4; nt++) {
                        if (nt >= NT) break;
                        const uint32_t* BH = &bh[nt >> 1][(nt & 1) * 2];
                        const uint32_t* BL = &bl[nt >> 1][(nt & 1) * 2];
                        mma16816(d[0][nt], ahi, BH);
                        mma16816(d[1][nt], ahi, BL);
                        mma16816(d[2][nt], alo, BH);
                    }
                }
                __syncthreads();
                if (tid == 0 && c + 2 < NC) {
                    waitc(c + 2);
                    mbar_tx(mb[bf], CHB);
                    bulk(stg[bf], src(c + 2), CHB, mb[bf]);
                }
            }

            // ---- epilogue: sum terms, leaky update, stage in smem ----
            #pragma unroll
            for (int nt = 0; nt < 4; nt++) {
                if (nt >= NT) break;
                #pragma unroll
                for (int j = 0; j < 4; j++) {
                    int hl = h0w + (lane >> 2) + (j >> 1) * 8;
                    int bb = bn + nt * 8 + (lane & 3) * 2 + (j & 1);
                    float add;
                    if (r0) add = g_xin0[((size_t)t * H + h0blk + hl) * B + bb];
                    else    add = (j >> 1) ? b1b : b1a;
                    float dv = d[0][nt][j] + d[1][nt][j] + d[2][nt][j];
                    float nv = OMA * v[nt][j] + AL * (dv + add);
                    v[nt][j] = nv;
                    float fr = fmaxf(nv, 0.f);
                    epf[bb * Wd + hl] = fr;
                    __nv_bfloat16 hi = __float2bfloat16(fr);
                    ehi[bb * Wd + hl] = hi;
                    elo[bb * Wd + hl] = __float2bfloat16(fr - __bfloat162float(hi));
                }
            }
            __syncthreads();

            // image writes first (these gate the consumers)
            {
                const int bb = tid >> 1, half = tid & 1;
                unsigned char* img = r0 ? g_f0img[p + 1][mychunk]
                                        : g_f1img[t + 1][mychunk];
                const int ub0 = (h0blk & 127) >> 3;
                const int upt = (Wd >> 3) >> 1;        // units per thread
                #pragma unroll
                for (int uu = 0; uu < 2; uu++) {
                    if (uu >= upt) break;
                    int ul = half * upt + uu;
                    int ug = ub0 + ul;
                    unsigned dsto = (unsigned)bb * 256 + ((unsigned)(ug ^ (bb & 7)) << 4);
                    uint4 hv = *(const uint4*)((const unsigned char*)ehi + bb * Wd * 2 + ul * 16);
                    uint4 lv = *(const uint4*)((const unsigned char*)elo + bb * Wd * 2 + ul * 16);
                    *(uint4*)(img + dsto) = hv;
                    *(uint4*)(img + 16384 + dsto) = lv;
                }
            }
            __syncthreads();
            if (tid == 0) {   // release: all block writes above are cumulative-visible
                __threadfence();
                if (r0) atomicAdd(&g_fl0[p + 1][mychunk], 1u);
                else    atomicAdd(&g_fl1[t + 1][mychunk], 1u);
            }
            // d_out states stores (no in-kernel consumer) off the critical path
            {
                const int bb = tid >> 1, half = tid & 1;
                float* st = r0 ? st0 : st1;
                const float* srow = epf + bb * Wd + half * (Wd / 2);
                float* drow = st + ((size_t)bb * T + t) * H + h0blk + half * (Wd / 2);
                #pragma unroll
                for (int q = 0; q < 4; q++) {
                    if (q >= Wd / 8) break;
                    ((float4*)drow)[q] = ((const float4*)srow)[q];
                }
            }
            __syncthreads();   // epf/staging free before next phase's TMA
        }
    }
}

// ---------------------------------------------------------------------------
// fp32 tiled GEMM: mode0 = xin0 (A=Win0, B=x per-t -> g_xin0), mode1 = output
// ---------------------------------------------------------------------------
__global__ void __launch_bounds__(256)
gemm_fp32(int mode, const float* __restrict__ A, const float* __restrict__ Bm,
          const float* __restrict__ bias, float* __restrict__ C)
{
    __shared__ float aS[16 * 64], bS[16 * 64];
    const int tid = threadIdx.x, m0 = blockIdx.x * 64;
    const int t = blockIdx.y, n0 = mode ? blockIdx.z * 64 : 0;
    const int lr = tid >> 2, lk = (tid & 3) * 4;
    const int tm4 = (tid >> 4) * 4, tn4 = (tid & 15) * 4;
    const int K = mode ? H : DIN;
    float acc[4][4] = {};
    const float* ap; const float* bp;
    if (mode) { ap = A + (size_t)(m0 + lr) * H + lk; bp = Bm + (size_t)(n0 + lr) * H + lk; }
    else      { ap = A + (size_t)(m0 + lr) * DIN + lk; bp = Bm + ((size_t)lr * T + t) * DIN + lk; }

    for (int k0 = 0; k0 < K; k0 += 16) {
        float4 av = *(const float4*)(ap + k0);
        float4 bv = *(const float4*)(bp + k0);
        __syncthreads();
        aS[(lk+0)*64+lr]=av.x; aS[(lk+1)*64+lr]=av.y; aS[(lk+2)*64+lr]=av.z; aS[(lk+3)*64+lr]=av.w;
        bS[(lk+0)*64+lr]=bv.x; bS[(lk+1)*64+lr]=bv.y; bS[(lk+2)*64+lr]=bv.z; bS[(lk+3)*64+lr]=bv.w;
        __syncthreads();
        #pragma unroll
        for (int kk = 0; kk < 16; kk++) {
            float4 a = *(const float4*)&aS[kk*64+tm4];
            float4 b = *(const float4*)&bS[kk*64+tn4];
            acc[0][0]+=a.x*b.x; acc[0][1]+=a.x*b.y; acc[0][2]+=a.x*b.z; acc[0][3]+=a.x*b.w;
            acc[1][0]+=a.y*b.x; acc[1][1]+=a.y*b.y; acc[1][2]+=a.y*b.z; acc[1][3]+=a.y*b.w;
            acc[2][0]+=a.z*b.x; acc[2][1]+=a.z*b.y; acc[2][2]+=a.z*b.z; acc[2][3]+=a.z*b.w;
            acc[3][0]+=a.w*b.x; acc[3][1]+=a.w*b.y; acc[3][2]+=a.w*b.z; acc[3][3]+=a.w*b.w;
        }
    }
    if (mode) {
        float4 bb = *(const float4*)&bias[n0 + tn4];
        #pragma unroll
        for (int i = 0; i < 4; i++) {
            int gm = m0 + tm4 + i;
            float4 o = make_float4(acc[i][0]+bb.x, acc[i][1]+bb.y, acc[i][2]+bb.z, acc[i][3]+bb.w);
            *(float4*)&C[(size_t)gm * DOUT + n0 + tn4] = o;
        }
    } else {
        #pragma unroll
        for (int i = 0; i < 4; i++) {
            float bb = bias[m0 + tm4 + i];
            float4 o = make_float4(acc[i][0]+bb, acc[i][1]+bb, acc[i][2]+bb, acc[i][3]+bb);
            *(float4*)&g_xin0[((size_t)t * H + m0 + tm4 + i) * B + tn4] = o;
        }
    }
}

// ---------------------------------------------------------------------------
extern "C" void kernel_launch(void* const* d_in, const int* in_sizes, int n_in,
                              void* d_out, int out_size)
{
    (void)in_sizes; (void)n_in; (void)out_size;
    const float* x     = (const float*)d_in[0];
    const float* Win0  = (const float*)d_in[1];
    const float* Wrec0 = (const float*)d_in[2];
    const float* b0    = (const float*)d_in[3];
    const float* Win1  = (const float*)d_in[4];
    const float* Wrec1 = (const float*)d_in[5];
    const float* b1    = (const float*)d_in[6];
    const float* Wout  = (const float*)d_in[7];
    const float* bout  = (const float*)d_in[8];

    float* out = (float*)d_out;
    float* states0 = out + (size_t)B * T * DOUT;
    float* states1 = states0 + (size_t)B * T * H;

    cudaFuncSetAttribute(rnn_mma, cudaFuncAttributeMaxDynamicSharedMemorySize, SMEM_T);

    gemm_fp32<<<dim3(H / 64, T, 1), 256>>>(0, Win0, x, b0, nullptr);
    rnn_mma<<<NBLK, THR, SMEM_T>>>(Wrec0, Wrec1, Win1, b1, states0, states1);
    gemm_fp32<<<dim3((B * T) / 64, 1, DOUT / 64), 256>>>(1, states1, Wout, bout, out);
}

// round 17
// speedup vs baseline: 1.1235x; 1.1235x over previous
#include <cuda_runtime.h>
#include <cuda_bf16.h>
#include <cstdint>

// ---------------------------------------------------------------------------
// Leaky CTRNN scan on HMMA (mma.sync m16n8k16 bf16, 3-term split).
// B=64 T=512 H=1024.  96 persistent blocks x 128 thr, 513 phases:
//   role0 (blk  0-31): fr0(p)   = relu(v0=.9v0+.1(Wrec0@fr0(p-1) + xin0)), K=1024
//   role1 (blk 32-95): fr1(p-1) = relu(v1=.9v1+.1([Wrec1|Win1]@[fr1(p-2);fr0(p-1)] + b1)), K=2048
// v17 = R14 champion + d_out stores moved into the grid-barrier shadow,
// plus retiled side GEMMs (128x64 tile, 8x4 microtile) to relieve LDS.
// ---------------------------------------------------------------------------

namespace {
constexpr int B = 64, T = 512, DIN = 256, H = 1024, DOUT = 256;
constexpr float AL = 0.1f, OMA = 0.9f;
constexpr int NBLK = 96, THR = 128;
constexpr int CHB = 32768;               // fr chunk bytes: [2][64][256]
constexpr int SM_W  = 0;                 // weights: 131072 bytes
constexpr int SM_ST = 131072;            // staging: 2 x CHB
constexpr int SM_MB = SM_ST + 2 * CHB;   // 196608: two mbarriers
constexpr int SMEM_T = SM_MB + 64;
}

// GMEM scratch (allocation-free rule)
__device__ float g_xin0[(size_t)T * H * B];                  // [t][h][b]
__device__ __align__(128) unsigned char g_f0img[513][8][CHB]; // slot t+1
__device__ __align__(128) unsigned char g_f1img[513][8][CHB];
__device__ volatile unsigned g_gen;
__device__ unsigned g_cnt;

// ---- PTX helpers ------------------------------------------------------------
__device__ __forceinline__ void mbar_init(unsigned m, unsigned c) {
    asm volatile("mbarrier.init.shared.b64 [%0], %1;" :: "r"(m), "r"(c) : "memory");
}
__device__ __forceinline__ void mbar_tx(unsigned m, unsigned b) {
    asm volatile("mbarrier.arrive.expect_tx.shared.b64 _, [%0], %1;" :: "r"(m), "r"(b) : "memory");
}
__device__ __forceinline__ void bulk(unsigned d, const void* s, unsigned b, unsigned m) {
    asm volatile("cp.async.bulk.shared::cta.global.mbarrier::complete_tx::bytes [%0], [%1], %2, [%3];"
                 :: "r"(d), "l"(s), "r"(b), "r"(m) : "memory");
}
__device__ __forceinline__ void mwait(unsigned m, unsigned p) {
    asm volatile("{\n\t.reg .pred P;\nL_%=:\n\tmbarrier.try_wait.parity.shared.b64 P, [%0], %1;\n\t@!P bra L_%=;\n\t}"
                 :: "r"(m), "r"(p) : "memory");
}
__device__ __forceinline__ void ldsm4(uint32_t* r, unsigned a) {
    asm volatile("ldmatrix.sync.aligned.m8n8.x4.shared.b16 {%0,%1,%2,%3}, [%4];"
                 : "=r"(r[0]), "=r"(r[1]), "=r"(r[2]), "=r"(r[3]) : "r"(a));
}
__device__ __forceinline__ void mma16816(float* d, const uint32_t* a, const uint32_t* b) {
    asm volatile("mma.sync.aligned.m16n8k16.row.col.f32.bf16.bf16.f32 "
                 "{%0,%1,%2,%3},{%4,%5,%6,%7},{%8,%9},{%0,%1,%2,%3};"
                 : "+f"(d[0]), "+f"(d[1]), "+f"(d[2]), "+f"(d[3])
                 : "r"(a[0]), "r"(a[1]), "r"(a[2]), "r"(a[3]), "r"(b[0]), "r"(b[1]));
}

__global__ void prep_zero() {
    const size_t n = 8ull * CHB / 16;     // one t-slot per image
    float4 z = make_float4(0.f, 0.f, 0.f, 0.f);
    for (size_t i = blockIdx.x * blockDim.x + threadIdx.x; i < n;
         i += (size_t)gridDim.x * blockDim.x) {
        ((float4*)&g_f0img[0][0][0])[i] = z;
        ((float4*)&g_f1img[0][0][0])[i] = z;
    }
}

// ---------------------------------------------------------------------------
__global__ void __launch_bounds__(THR, 1)
rnn_mma(const float* __restrict__ Wrec0, const float* __restrict__ Wrec1,
        const float* __restrict__ Win1, const float* __restrict__ b1,
        float* __restrict__ st0, float* __restrict__ st1)
{
    extern __shared__ unsigned char smc[];
    const unsigned sb = (unsigned)__cvta_generic_to_shared(smc);
    const int tid = threadIdx.x, wid = tid >> 5, lane = tid & 31, bid = blockIdx.x;
    const bool r0 = (bid < 32);
    const int HR = r0 ? 32 : 16;          // weight rows in smem tile
    const int PW = HR * 256;              // weight plane bytes
    const int CW = 2 * PW;                // weight chunk bytes
    const int NC = r0 ? 8 : 16;           // k-chunks per phase
    const int h0blk = r0 ? bid * 32 : (bid - 32) * 16;
    const int h0w = r0 ? (wid >> 1) * 16 : 0;      // warp m base (block-local)
    const int bn  = r0 ? (wid & 1) * 32 : wid * 16; // warp n base
    const int NT  = r0 ? 4 : 2;           // n8 tiles per warp
    const int NBF = NT >> 1;              // B ldmatrix.x4 per plane

    // --- one-time: weights -> smem bf16 hi/lo, ldmatrix-swizzled ---
    {
        const int KT = r0 ? 1024 : 2048;
        for (int i = tid; i < HR * KT; i += THR) {
            int hl = i / KT, k = i - hl * KT;
            float val;
            if (r0) val = Wrec0[(size_t)(h0blk + hl) * H + k];
            else    val = (k < H) ? Wrec1[(size_t)(h0blk + hl) * H + k]
                                  : Win1[(size_t)(h0blk + hl) * H + (k - H)];
            __nv_bfloat16 hi = __float2bfloat16(val);
            __nv_bfloat16 lo = __float2bfloat16(val - __bfloat162float(hi));
            int c = k >> 7, kl = k & 127, u = kl >> 3;
            unsigned off = SM_W + (unsigned)c * CW + (unsigned)hl * 256
                         + ((unsigned)(u ^ (hl & 7)) << 4) + (kl & 7) * 2;
            *(__nv_bfloat16*)(smc + off) = hi;
            *(__nv_bfloat16*)(smc + off + PW) = lo;
        }
    }
    if (tid == 0) { mbar_init(sb + SM_MB, 1); mbar_init(sb + SM_MB + 8, 1); }
    asm volatile("fence.proxy.async.shared::cta;" ::: "memory");
    __syncthreads();

    // fragment address precompute
    const int ar  = h0w + (lane & 7) + ((lane >> 3) & 1) * 8;  // A row
    const int akh = (lane >> 4) & 1;
    const int ar7 = ar & 7;
    int brr[2], br7[2];
    #pragma unroll
    for (int f = 0; f < 2; f++) {
        brr[f] = bn + f * 16 + (lane & 7) + ((lane >> 4) & 1) * 8;
        br7[f] = brr[f] & 7;
    }
    const int bkh = (lane >> 3) & 1;

    float b1a = 0.f, b1b = 0.f;
    if (!r0) { b1a = b1[h0blk + (lane >> 2)]; b1b = b1[h0blk + (lane >> 2) + 8]; }

    unsigned par[2] = {0, 0};
    const unsigned mb[2]  = {sb + SM_MB, sb + SM_MB + 8};
    const unsigned stg[2] = {sb + SM_ST, sb + SM_ST + CHB};

    // epilogue staging views (buffer 0 region)
    const int Wd = r0 ? 32 : 16;
    float* epf = (float*)(smc + SM_ST);
    __nv_bfloat16* ehi = (__nv_bfloat16*)(smc + SM_ST + 64 * Wd * 4);
    __nv_bfloat16* elo = ehi + 64 * Wd;

    float v[4][4];
    #pragma unroll
    for (int i = 0; i < 4; i++)
        #pragma unroll
        for (int j = 0; j < 4; j++) v[i][j] = 0.f;

    for (int p = 0; p <= T; p++) {
        const int t = r0 ? p : (p - 1);
        const bool act = r0 ? (p < T) : (p >= 1);
        if (act) {
            auto src = [&](int c) -> const void* {
                if (r0) return (const void*)g_f0img[p][c];        // fr0(p-1)
                return (c < 8) ? (const void*)g_f1img[t][c]        // fr1(t-1)
                               : (const void*)g_f0img[p][c - 8];   // fr0(p-1)
            };
            if (tid == 0) {
                #pragma unroll
                for (int c = 0; c < 2; c++) {
                    mbar_tx(mb[c], CHB);
                    bulk(stg[c], src(c), CHB, mb[c]);
                }
            }
            // 3 separate accumulator sets: 0 = hi*hi, 1 = hi*lo, 2 = lo*hi
            float d[3][4][4];
            #pragma unroll
            for (int e = 0; e < 3; e++)
                #pragma unroll
                for (int i = 0; i < 4; i++)
                    #pragma unroll
                    for (int j = 0; j < 4; j++) d[e][i][j] = 0.f;

            for (int c = 0; c < NC; c++) {
                const int bf = c & 1;
                mwait(mb[bf], par[bf]); par[bf] ^= 1;
                const unsigned wb = sb + SM_W + (unsigned)c * CW;
                const unsigned sg = stg[bf];
                #pragma unroll
                for (int ks = 0; ks < 8; ks++) {
                    uint32_t ahi[4], alo[4], bh[2][4], bl[2][4];
                    unsigned ua = ((unsigned)((ks * 2 + akh) ^ ar7)) << 4;
                    ldsm4(ahi, wb + (unsigned)ar * 256 + ua);
                    ldsm4(alo, wb + PW + (unsigned)ar * 256 + ua);
                    #pragma unroll
                    for (int f = 0; f < 2; f++) {
                        if (f >= NBF) break;
                        unsigned ub = ((unsigned)((ks * 2 + bkh) ^ br7[f])) << 4;
                        unsigned ba = sg + (unsigned)brr[f] * 256 + ub;
                        ldsm4(bh[f], ba);
                        ldsm4(bl[f], ba + 16384);
                    }
                    #pragma unroll
                    for (int nt = 0; nt < 4; nt++) {
                        if (nt >= NT) break;
                        const uint32_t* BH = &bh[nt >> 1][(nt & 1) * 2];
                        const uint32_t* BL = &bl[nt >> 1][(nt & 1) * 2];
                        mma16816(d[0][nt], ahi, BH);
                        mma16816(d[1][nt], ahi, BL);
                        mma16816(d[2][nt], alo, BH);
                    }
                }
                __syncthreads();
                if (tid == 0 && c + 2 < NC) {
                    mbar_tx(mb[bf], CHB);
                    bulk(stg[bf], src(c + 2), CHB, mb[bf]);
                }
            }

            // ---- epilogue: sum terms, leaky update, stage, image writes ----
            #pragma unroll
            for (int nt = 0; nt < 4; nt++) {
                if (nt >= NT) break;
                #pragma unroll
                for (int j = 0; j < 4; j++) {
                    int hl = h0w + (lane >> 2) + (j >> 1) * 8;
                    int bb = bn + nt * 8 + (lane & 3) * 2 + (j & 1);
                    float add;
                    if (r0) add = g_xin0[((size_t)t * H + h0blk + hl) * B + bb];
                    else    add = (j >> 1) ? b1b : b1a;
                    float dv = d[0][nt][j] + d[1][nt][j] + d[2][nt][j];
                    float nv = OMA * v[nt][j] + AL * (dv + add);
                    v[nt][j] = nv;
                    float fr = fmaxf(nv, 0.f);
                    epf[bb * Wd + hl] = fr;
                    __nv_bfloat16 hi = __float2bfloat16(fr);
                    ehi[bb * Wd + hl] = hi;
                    elo[bb * Wd + hl] = __float2bfloat16(fr - __bfloat162float(hi));
                }
            }
            __syncthreads();
            {
                const int bb = tid >> 1, half = tid & 1;
                unsigned char* img = r0 ? g_f0img[p + 1][h0blk >> 7]
                                        : g_f1img[t + 1][h0blk >> 7];
                const int ub0 = (h0blk & 127) >> 3;
                const int upt = (Wd >> 3) >> 1;        // units per thread
                #pragma unroll
                for (int uu = 0; uu < 2; uu++) {
                    if (uu >= upt) break;
                    int ul = half * upt + uu;
                    int ug = ub0 + ul;
                    unsigned dsto = (unsigned)bb * 256 + ((unsigned)(ug ^ (bb & 7)) << 4);
                    uint4 hv = *(const uint4*)((const unsigned char*)ehi + bb * Wd * 2 + ul * 16);
                    uint4 lv = *(const uint4*)((const unsigned char*)elo + bb * Wd * 2 + ul * 16);
                    *(uint4*)(img + dsto) = hv;
                    *(uint4*)(img + 16384 + dsto) = lv;
                }
            }
        }

        if (p < T) {
            // grid barrier: arrive first; d_out states stores hidden under wait
            __syncthreads();
            unsigned g = 0;
            if (tid == 0) {
                __threadfence();
                g = g_gen;
                if (atomicAdd(&g_cnt, 1u) == NBLK - 1) {
                    g_cnt = 0; __threadfence(); g_gen = g + 1;
                }
            }
            if (act) {   // states store (not consumed in-kernel)
                const int bb = tid >> 1, half = tid & 1;
                float* st = r0 ? st0 : st1;
                const float* srow = epf + bb * Wd + half * (Wd / 2);
                float* drow = st + ((size_t)bb * T + t) * H + h0blk + half * (Wd / 2);
                #pragma unroll
                for (int q = 0; q < 4; q++) {
                    if (q >= Wd / 8) break;
                    ((float4*)drow)[q] = ((const float4*)srow)[q];
                }
            }
            if (tid == 0) {
                while (g_gen == g) {}
                __threadfence();
            }
            __syncthreads();
        } else if (act) {   // last phase: just store
            const int bb = tid >> 1, half = tid & 1;
            float* st = r0 ? st0 : st1;
            const float* srow = epf + bb * Wd + half * (Wd / 2);
            float* drow = st + ((size_t)bb * T + t) * H + h0blk + half * (Wd / 2);
            #pragma unroll
            for (int q = 0; q < 4; q++) {
                if (q >= Wd / 8) break;
                ((float4*)drow)[q] = ((const float4*)srow)[q];
            }
        }
    }
}

// ---------------------------------------------------------------------------
// fp32 tiled GEMM, 128x64 tile, 8x4 microtile (LDS-relief retile).
// mode0: xin0 (A=Win0 [H,DIN], B=x per-t [B,T,DIN] -> g_xin0[t][h][b])
// mode1: output (A=states1 [B*T,H], B=Wout [DOUT,H] -> out[B*T,DOUT])
// ---------------------------------------------------------------------------
__global__ void __launch_bounds__(256)
gemm_fp32(int mode, const float* __restrict__ A, const float* __restrict__ Bm,
          const float* __restrict__ bias, float* __restrict__ C)
{
    __shared__ float aS[16 * 128];
    __shared__ float bS[16 * 64];
    const int tid = threadIdx.x;
    const int m0 = blockIdx.x * 128;
    const int t  = blockIdx.y;
    const int n0 = mode ? blockIdx.z * 64 : 0;
    const int K  = mode ? H : DIN;
    const int alr = tid >> 1, alk = (tid & 1) * 8;     // A loader: 2 float4
    const int blr = tid & 63, blk = (tid >> 6) * 4;    // B loader: 1 float4
    const int tm8 = (tid >> 4) * 8;
    const int tn4 = (tid & 15) * 4;
    const float* ap; const float* bp;
    if (mode) { ap = A + (size_t)(m0 + alr) * H + alk;
                bp = Bm + (size_t)(n0 + blr) * H + blk; }
    else      { ap = A + (size_t)(m0 + alr) * DIN + alk;
                bp = Bm + ((size_t)blr * T + t) * DIN + blk; }

    float acc[8][4] = {};
    for (int k0 = 0; k0 < K; k0 += 16) {
        float4 a0 = *(const float4*)(ap + k0);
        float4 a1 = *(const float4*)(ap + k0 + 4);
        float4 bv = *(const float4*)(bp + k0);
        __syncthreads();
        aS[(alk+0)*128+alr]=a0.x; aS[(alk+1)*128+alr]=a0.y;
        aS[(alk+2)*128+alr]=a0.z; aS[(alk+3)*128+alr]=a0.w;
        aS[(alk+4)*128+alr]=a1.x; aS[(alk+5)*128+alr]=a1.y;
        aS[(alk+6)*128+alr]=a1.z; aS[(alk+7)*128+alr]=a1.w;
        bS[(blk+0)*64+blr]=bv.x; bS[(blk+1)*64+blr]=bv.y;
        bS[(blk+2)*64+blr]=bv.z; bS[(blk+3)*64+blr]=bv.w;
        __syncthreads();
        #pragma unroll
        for (int kk = 0; kk < 16; kk++) {
            float4 x0 = *(const float4*)&aS[kk*128 + tm8];
            float4 x1 = *(const float4*)&aS[kk*128 + tm8 + 4];
            float4 y  = *(const float4*)&bS[kk*64 + tn4];
            float am[8] = {x0.x, x0.y, x0.z, x0.w, x1.x, x1.y, x1.z, x1.w};
            #pragma unroll
            for (int i = 0; i < 8; i++) {
                acc[i][0] += am[i] * y.x; acc[i][1] += am[i] * y.y;
                acc[i][2] += am[i] * y.z; acc[i][3] += am[i] * y.w;
            }
        }
    }
    if (mode) {
        float4 bb = *(const float4*)&bias[n0 + tn4];
        #pragma unroll
        for (int i = 0; i < 8; i++) {
            int gm = m0 + tm8 + i;
            float4 o = make_float4(acc[i][0]+bb.x, acc[i][1]+bb.y,
                                   acc[i][2]+bb.z, acc[i][3]+bb.w);
            *(float4*)&C[(size_t)gm * DOUT + n0 + tn4] = o;
        }
    } else {
        #pragma unroll
        for (int i = 0; i < 8; i++) {
            int row = m0 + tm8 + i;
            float bb = bias[row];
            float4 o = make_float4(acc[i][0]+bb, acc[i][1]+bb,
                                   acc[i][2]+bb, acc[i][3]+bb);
            *(float4*)&g_xin0[((size_t)t * H + row) * B + tn4] = o;
        }
    }
}

// ---------------------------------------------------------------------------
extern "C" void kernel_launch(void* const* d_in, const int* in_sizes, int n_in,
                              void* d_out, int out_size)
{
    (void)in_sizes; (void)n_in; (void)out_size;
    const float* x     = (const float*)d_in[0];
    const float* Win0  = (const float*)d_in[1];
    const float* Wrec0 = (const float*)d_in[2];
    const float* b0    = (const float*)d_in[3];
    const float* Win1  = (const float*)d_in[4];
    const float* Wrec1 = (const float*)d_in[5];
    const float* b1    = (const float*)d_in[6];
    const float* Wout  = (const float*)d_in[7];
    const float* bout  = (const float*)d_in[8];

    float* out = (float*)d_out;
    float* states0 = out + (size_t)B * T * DOUT;
    float* states1 = states0 + (size_t)B * T * H;

    cudaFuncSetAttribute(rnn_mma, cudaFuncAttributeMaxDynamicSharedMemorySize, SMEM_T);

    prep_zero<<<128, 256>>>();
    gemm_fp32<<<dim3(H / 128, T, 1), 256>>>(0, Win0, x, b0, nullptr);
    rnn_mma<<<NBLK, THR, SMEM_T>>>(Wrec0, Wrec1, Win1, b1, states0, states1);
    gemm_fp32<<<dim3((B * T) / 128, 1, DOUT / 64), 256>>>(1, states1, Wout, bout, out);
}